// round 13
// baseline (speedup 1.0000x reference)
#include <cuda_runtime.h>
#include <cstdint>
#include <math.h>

#define KSEL 100
#define NTHREADS 512
#define NWARPS (NTHREADS / 32)
#define FTHREADS 256
#define CHUNK 4096
#define EPT_F (CHUNK / FTHREADS)     // 16 elements per filter thread
#define CAND_MAX 512
#define NTASKS 192
#define SAMPLE_NUM 10

__device__ unsigned long long g_cand[NTASKS * CAND_MAX];   // 768 KB
__device__ int g_cnt[NTASKS];

__device__ __forceinline__ uint32_t f2key(float f) {
    uint32_t u = __float_as_uint(f);
    return (u & 0x80000000u) ? ~u : (u | 0x80000000u);
}

// ---------------------------------------------------------------- zero
__global__ void zero_kernel() {
    if (threadIdx.x < NTASKS) g_cnt[threadIdx.x] = 0;
}

// ---------------------------------------------------------------- filter
__global__ __launch_bounds__(FTHREADS) void filter_kernel(
    const float* __restrict__ blk_logits,
    const float* __restrict__ lin_logits,
    const float* __restrict__ chr_logits)
{
    const int b     = blockIdx.x;
    const int level = blockIdx.y;
    const int chunk = blockIdx.z;
    if (level == 0 && chunk > 0) return;          // level0 has one chunk

    const float* logits;
    int N; float t0f;
    if (level == 0)      { logits = blk_logits; N = 4096;  t0f = 1.60f; }
    else if (level == 1) { logits = lin_logits; N = 16384; t0f = 2.15f; }
    else                 { logits = chr_logits; N = 16384; t0f = 2.15f; }
    const uint32_t T0 = f2key(t0f);
    const int task = level * 64 + b;

    const int tid  = threadIdx.x;
    const int lane = tid & 31;
    const int base_el = chunk * CHUNK;
    const float4* lg4 = (const float4*)(logits + (size_t)b * N + base_el);

    // load 16 elements (4 x float4), coalesced, high MLP
    float4 v[4];
    #pragma unroll
    for (int j = 0; j < 4; j++) v[j] = lg4[tid + FTHREADS * j];

    uint32_t keys[16];
    #pragma unroll
    for (int j = 0; j < 4; j++) {
        keys[4 * j + 0] = f2key(v[j].x);
        keys[4 * j + 1] = f2key(v[j].y);
        keys[4 * j + 2] = f2key(v[j].z);
        keys[4 * j + 3] = f2key(v[j].w);
    }

    int myc = 0;
    #pragma unroll
    for (int e = 0; e < 16; e++) myc += (keys[e] >= T0) ? 1 : 0;

    // warp exclusive scan of myc
    int pre = myc;
    #pragma unroll
    for (int d = 1; d < 32; d <<= 1) {
        int t2 = __shfl_up_sync(0xffffffffu, pre, d);
        if (lane >= d) pre += t2;
    }
    int wtot = __shfl_sync(0xffffffffu, pre, 31);
    int myoff = pre - myc;
    int wbase = 0;
    if (lane == 31 && wtot > 0) wbase = atomicAdd(&g_cnt[task], wtot);
    wbase = __shfl_sync(0xffffffffu, wbase, 31);

    if (myc > 0) {
        int pos = wbase + myoff;
        unsigned long long* dst = &g_cand[(size_t)task * CAND_MAX];
        #pragma unroll
        for (int e = 0; e < 16; e++) {
            if (keys[e] >= T0) {
                if (pos < CAND_MAX) {
                    int gi = base_el + 4 * (tid + FTHREADS * (e >> 2)) + (e & 3);
                    dst[pos] = ~(((unsigned long long)keys[e] << 32) |
                                 (unsigned long long)(0xFFFFFFFFu - (uint32_t)gi));
                }
                pos++;
            }
        }
    }
}

// ---------------------------------------------------------------- epilogue
__global__ __launch_bounds__(NTHREADS) void epilogue_kernel(
    const float* __restrict__ blk_logits,
    const float* __restrict__ lin_logits,
    const float* __restrict__ chr_logits,
    const float* __restrict__ blk_raw,
    const float* __restrict__ lin_raw,
    const float* __restrict__ chr_raw,
    const float* __restrict__ tsizes,
    float* __restrict__ out)
{
    __shared__ int       sPart[2][NWARPS];
    __shared__ unsigned long long sCand[CAND_MAX];
    __shared__ int       sCandCnt;
    __shared__ float     sVal[KSEL];
    __shared__ int       sIdx[KSEL];
    __shared__ float     sData[KSEL * 16];
    __shared__ float     sBox[KSEL * 4];
    __shared__ float     sArea[KSEL];
    __shared__ int       sKeep[KSEL];
    __shared__ float     sBelong[KSEL];
    __shared__ int       sFb;

    const int b     = blockIdx.x;
    const int level = blockIdx.y;
    const int tid   = threadIdx.x;
    const int lane  = tid & 31;
    const int wid   = tid >> 5;
    const int task  = level * 64 + b;

    const float* logits;
    const float* raw;
    const float* parent = nullptr;
    int N, parentN = 0, ef = 1;
    bool bez = false;
    int data_off, score_off, keep_off, dd;

    if (level == 0) {
        logits = blk_logits; raw = blk_raw; N = 4096; dd = 4;
        data_off = 0;      score_off = 25600;  keep_off = 32000;
    } else if (level == 1) {
        logits = lin_logits; raw = lin_raw; parent = blk_raw; parentN = 4096; ef = 4;
        N = 16384; dd = 4;
        data_off = 38400;  score_off = 64000;  keep_off = 70400;
    } else {
        logits = chr_logits; raw = chr_raw; parent = lin_raw; parentN = 16384; ef = 1;
        N = 16384; dd = 16; bez = true;
        data_off = 76800;  score_off = 179200; keep_off = 185600;
    }

    const float img_h = tsizes[2 * b + 0];
    const float img_w = tsizes[2 * b + 1];
    const float* lg = logits + (size_t)b * N;
    const float4* lg4 = (const float4*)lg;
    const int N4 = N >> 2;

    int cnt = g_cnt[task];

    if (cnt >= KSEL && cnt <= CAND_MAX) {
        // ---- fast path: pull candidates from global buffer ----
        if (tid < cnt) sCand[tid] = g_cand[(size_t)task * CAND_MAX + tid];
        __syncthreads();
    } else {
        // ---- fallback: bisection over full logits (arbitrary data) ----
        uint32_t lo = 0u, hi = 0xFFFFFFFFu, T = 0u;
        for (int it = 0; it < 34; it++) {
            uint32_t mid = lo + ((hi - lo) >> 1);
            int c = 0;
            #pragma unroll
            for (int j = 0; j < 8; j++) {
                int i4 = tid + NTHREADS * j;
                if (i4 < N4) {
                    float4 v = lg4[i4];
                    c += (f2key(v.x) >= mid) + (f2key(v.y) >= mid)
                       + (f2key(v.z) >= mid) + (f2key(v.w) >= mid);
                }
            }
            #pragma unroll
            for (int d = 16; d > 0; d >>= 1)
                c += __shfl_down_sync(0xffffffffu, c, d);
            if (lane == 0) sPart[it & 1][wid] = c;
            __syncthreads();
            int tot = 0;
            #pragma unroll
            for (int w = 0; w < NWARPS; w++) tot += sPart[it & 1][w];
            if (tot >= KSEL && tot <= CAND_MAX) { T = mid; break; }
            if (tot > CAND_MAX) lo = mid; else hi = mid;
            if (hi - lo <= 1u) { T = lo; break; }
        }
        if (tid == 0) sCandCnt = 0;
        __syncthreads();
        #pragma unroll
        for (int j = 0; j < 8; j++) {
            int i4 = tid + NTHREADS * j;
            if (i4 < N4) {
                float4 v = lg4[i4];
                float e[4] = {v.x, v.y, v.z, v.w};
                #pragma unroll
                for (int q = 0; q < 4; q++) {
                    uint32_t kk = f2key(e[q]);
                    if (kk >= T) {
                        int gi = 4 * i4 + q;
                        int pos = atomicAdd(&sCandCnt, 1);
                        if (pos < CAND_MAX)
                            sCand[pos] = ~(((unsigned long long)kk << 32) |
                                           (unsigned long long)(0xFFFFFFFFu - (uint32_t)gi));
                    }
                }
            }
        }
        __syncthreads();
        cnt = min(sCandCnt, CAND_MAX);
    }

    // ---- enumeration sort: rank & scatter top-100 ----
    if (tid < KSEL) { sVal[tid] = 0.0f; sIdx[tid] = 0; }
    __syncthreads();
    if (tid < cnt) {
        unsigned long long mine = sCand[tid];
        int rank = 0;
        int j = 0;
        for (; j + 3 < cnt; j += 4)
            rank += (sCand[j]     < mine) + (sCand[j + 1] < mine)
                  + (sCand[j + 2] < mine) + (sCand[j + 3] < mine);
        for (; j < cnt; j++) rank += (sCand[j] < mine);
        if (rank < KSEL) {
            unsigned long long comb = ~mine;
            uint32_t kk  = (uint32_t)(comb >> 32);
            uint32_t idx = 0xFFFFFFFFu - (uint32_t)(comb & 0xFFFFFFFFull);
            sIdx[rank] = (int)idx;
            uint32_t u = (kk & 0x80000000u) ? (kk & 0x7FFFFFFFu) : ~kk;
            float lv = __uint_as_float(u);
            sVal[rank] = 1.0f / (1.0f + expf(-lv));
        }
    }
    __syncthreads();

    // ---- boxes / data ----
    if (tid < KSEL) {
        int si = sIdx[tid];
        if (!bez) {
            const float* r = raw + ((size_t)b * N + si) * 4;
            float cx = r[0], cy = r[1], w = r[2], h = r[3];
            float x1 = (cx - 0.5f * w) * img_w;
            float y1 = (cy - 0.5f * h) * img_h;
            float x2 = (cx + 0.5f * w) * img_w;
            float y2 = (cy + 0.5f * h) * img_h;
            if (level == 0) {
                x1 = fminf(fmaxf(x1, 0.0f), img_w);
                y1 = fminf(fmaxf(y1, 0.0f), img_h);
                x2 = fminf(fmaxf(x2, 0.0f), img_w);
                y2 = fminf(fmaxf(y2, 0.0f), img_h);
            }
            sData[tid * 16 + 0] = x1; sData[tid * 16 + 1] = y1;
            sData[tid * 16 + 2] = x2; sData[tid * 16 + 3] = y2;
            sBox[tid * 4 + 0] = x1; sBox[tid * 4 + 1] = y1;
            sBox[tid * 4 + 2] = x2; sBox[tid * 4 + 3] = y2;
            sArea[tid] = (x2 - x1) * (y2 - y1);
        } else {
            const float* r = raw + ((size_t)b * N + si) * 16;
            float cp0[8], cp1[8];
            #pragma unroll
            for (int f = 0; f < 8; f++) {
                cp0[f] = r[2 * f + 0] * img_h;          // scale_pts = tile((h,w),8)
                cp1[f] = r[2 * f + 1] * img_w;
                sData[tid * 16 + 2 * f + 0] = cp0[f];
                sData[tid * 16 + 2 * f + 1] = cp1[f];
            }
            float mn0 =  INFINITY, mn1 =  INFINITY;
            float mx0 = -INFINITY, mx1 = -INFINITY;
            #pragma unroll
            for (int s = 0; s < SAMPLE_NUM; s++) {
                float t  = (float)s / (float)(SAMPLE_NUM - 1);
                float ti = 1.0f - t;
                float b0c = ti * ti * ti;
                float b1c = 3.0f * t * ti * ti;
                float b2c = 3.0f * t * t * ti;
                float b3c = t * t * t;
                float px = b0c * cp0[0] + b1c * cp0[1] + b2c * cp0[2] + b3c * cp0[3];
                float py = b0c * cp1[0] + b1c * cp1[1] + b2c * cp1[2] + b3c * cp1[3];
                float qx = b0c * cp0[4] + b1c * cp0[5] + b2c * cp0[6] + b3c * cp0[7];
                float qy = b0c * cp1[4] + b1c * cp1[5] + b2c * cp1[6] + b3c * cp1[7];
                mn0 = fminf(mn0, fminf(px, qx));
                mn1 = fminf(mn1, fminf(py, qy));
                mx0 = fmaxf(mx0, fmaxf(px, qx));
                mx1 = fmaxf(mx1, fmaxf(py, qy));
            }
            sBox[tid * 4 + 0] = mn0; sBox[tid * 4 + 1] = mn1;
            sBox[tid * 4 + 2] = mx0; sBox[tid * 4 + 3] = mx1;
            sArea[tid] = (mx0 - mn0) * (mx1 - mn1);
        }
    }

    // ---- keep = vals > 0.1 (fallback to index 0) ----
    int keep0 = (tid < KSEL) ? (sVal[tid] > 0.1f ? 1 : 0) : 0;
    int any0 = __syncthreads_or(keep0);
    if (tid < KSEL) sKeep[tid] = any0 ? keep0 : (tid == 0 ? 1 : 0);

    // ---- parent belong filter (line / char) ----
    if (level > 0) {
        int valid = 0, mykeep = 0;
        if (tid < KSEL) {
            mykeep = sKeep[tid];
            int pi = sIdx[tid] / ef;
            const float* pr = parent + ((size_t)b * parentN + pi) * 4;
            float pcx = pr[0], pcy = pr[1], pw = pr[2], ph = pr[3];
            float px1 = (pcx - 0.5f * pw) * img_w;
            float py1 = (pcy - 0.5f * ph) * img_h;
            float px2 = (pcx + 0.5f * pw) * img_w;
            float py2 = (pcy + 0.5f * ph) * img_h;
            float bx1 = sBox[tid * 4 + 0], by1 = sBox[tid * 4 + 1];
            float bx2 = sBox[tid * 4 + 2], by2 = sBox[tid * 4 + 3];
            float ix1 = fmaxf(bx1, px1), iy1 = fmaxf(by1, py1);
            float ix2 = fminf(bx2, px2), iy2 = fminf(by2, py2);
            float inter = fmaxf(ix2 - ix1, 0.0f) * fmaxf(iy2 - iy1, 0.0f);
            float carea = (bx2 - bx1) * (by2 - by1);
            float belong = inter / (carea + 1e-6f);
            sBelong[tid] = belong;
            valid = (belong > 0.6f) ? 1 : 0;
        }
        int haveValid = __syncthreads_or(valid && mykeep);
        if (!haveValid) {
            if (tid == 0) {
                float best = -INFINITY; int bi = 0;
                for (int kk = 0; kk < KSEL; kk++) {
                    float v = sKeep[kk] ? sBelong[kk] : -INFINITY;
                    if (v > best) { best = v; bi = kk; }
                }
                sFb = bi;
            }
            __syncthreads();
            if (tid < KSEL) valid = (tid == sFb) ? 1 : 0;
        }
        if (tid < KSEL) sKeep[tid] &= valid;
    }
    __syncthreads();

    // ---- greedy NMS: warp 0, register-resident ----
    if (tid < 32) {
        float x1r[4], y1r[4], x2r[4], y2r[4], arr[4]; int kp[4];
        #pragma unroll
        for (int s = 0; s < 4; s++) {
            int idx = tid + 32 * s;
            if (idx < KSEL) {
                x1r[s] = sBox[idx * 4 + 0]; y1r[s] = sBox[idx * 4 + 1];
                x2r[s] = sBox[idx * 4 + 2]; y2r[s] = sBox[idx * 4 + 3];
                arr[s] = sArea[idx];        kp[s]  = sKeep[idx];
            } else {
                x1r[s] = 0.f; y1r[s] = 0.f; x2r[s] = 0.f; y2r[s] = 0.f;
                arr[s] = 0.f; kp[s] = 0;
            }
        }
        #pragma unroll
        for (int slot = 0; slot < 4; slot++) {
            const int lim = (slot < 3) ? 32 : (KSEL - 96);
            for (int o = 0; o < lim; o++) {
                int   ki  = __shfl_sync(0xffffffffu, kp[slot],  o);
                float ix1 = __shfl_sync(0xffffffffu, x1r[slot], o);
                float iy1 = __shfl_sync(0xffffffffu, y1r[slot], o);
                float ix2 = __shfl_sync(0xffffffffu, x2r[slot], o);
                float iy2 = __shfl_sync(0xffffffffu, y2r[slot], o);
                float iar = __shfl_sync(0xffffffffu, arr[slot], o);
                if (ki) {
                    int i = slot * 32 + o;
                    #pragma unroll
                    for (int s = 0; s < 4; s++) {
                        int idx = tid + 32 * s;
                        if (idx > i && idx < KSEL && kp[s]) {
                            float tx1 = fmaxf(ix1, x1r[s]);
                            float ty1 = fmaxf(iy1, y1r[s]);
                            float tx2 = fminf(ix2, x2r[s]);
                            float ty2 = fminf(iy2, y2r[s]);
                            float inter = fmaxf(tx2 - tx1, 0.0f) * fmaxf(ty2 - ty1, 0.0f);
                            float iou = inter / (iar + arr[s] - inter);
                            if (iou > 0.1f) kp[s] = 0;
                        }
                    }
                }
            }
        }
        #pragma unroll
        for (int s = 0; s < 4; s++) {
            int idx = tid + 32 * s;
            if (idx < KSEL) sKeep[idx] = kp[s];
        }
    }
    __syncthreads();

    // ---- write outputs ----
    if (tid < KSEL) {
        const int nk = sKeep[tid];
        for (int j = 0; j < dd; j++)
            out[data_off + ((size_t)b * KSEL + tid) * dd + j] =
                nk ? sData[tid * 16 + j] : 0.0f;
        out[score_off + (size_t)b * KSEL + tid] = nk ? sVal[tid] : 0.0f;
        out[keep_off  + (size_t)b * KSEL + tid] = nk ? 1.0f : 0.0f;
    }
}

extern "C" void kernel_launch(void* const* d_in, const int* in_sizes, int n_in,
                              void* d_out, int out_size) {
    const float* blk_logits = (const float*)d_in[0];
    const float* lin_logits = (const float*)d_in[1];
    const float* chr_logits = (const float*)d_in[2];
    const float* blk_raw    = (const float*)d_in[3];
    const float* lin_raw    = (const float*)d_in[4];
    const float* chr_raw    = (const float*)d_in[5];
    const float* tsizes     = (const float*)d_in[6];
    float* out = (float*)d_out;

    zero_kernel<<<1, NTASKS>>>();
    dim3 fgrid(64, 3, 4);
    filter_kernel<<<fgrid, FTHREADS>>>(blk_logits, lin_logits, chr_logits);
    dim3 egrid(64, 3);
    epilogue_kernel<<<egrid, NTHREADS>>>(
        blk_logits, lin_logits, chr_logits,
        blk_raw, lin_raw, chr_raw, tsizes, out);
}

// round 17
// speedup vs baseline: 1.2525x; 1.2525x over previous
#include <cuda_runtime.h>
#include <cstdint>
#include <math.h>

#define KSEL 100
#define NTHREADS 512
#define NWARPS (NTHREADS / 32)
#define CAND_MAX 512
#define SAMPLE_NUM 10

__device__ __forceinline__ uint32_t f2key(float f) {
    uint32_t u = __float_as_uint(f);
    return (u & 0x80000000u) ? ~u : (u | 0x80000000u);
}

__global__ __launch_bounds__(NTHREADS) void postprocess_kernel(
    const float* __restrict__ blk_logits,
    const float* __restrict__ lin_logits,
    const float* __restrict__ chr_logits,
    const float* __restrict__ blk_raw,
    const float* __restrict__ lin_raw,
    const float* __restrict__ chr_raw,
    const float* __restrict__ tsizes,
    float* __restrict__ out)
{
    __shared__ int       sPart[2][NWARPS];
    __shared__ unsigned long long sCand[CAND_MAX];
    __shared__ int       sCandCnt;
    __shared__ float     sVal[KSEL];
    __shared__ int       sIdx[KSEL];
    __shared__ float     sData[KSEL * 16];
    __shared__ float     sBox[KSEL * 4];
    __shared__ float     sArea[KSEL];
    __shared__ int       sKeep[KSEL];
    __shared__ float     sBelong[KSEL];
    __shared__ int       sFb;
    __shared__ __align__(16) uint32_t sSup[KSEL * 4];   // suppression bitmasks (16B rows)
    __shared__ uint32_t  sKw[4];                        // packed keep bits

    const int b     = blockIdx.x;
    const int level = blockIdx.y;
    const int tid   = threadIdx.x;
    const int lane  = tid & 31;
    const int wid   = tid >> 5;

    const float* logits;
    const float* raw;
    const float* parent = nullptr;
    int N, parentN = 0, ef = 1;
    bool bez = false;
    int data_off, score_off, keep_off, dd;
    float t0f;

    if (level == 0) {
        logits = blk_logits; raw = blk_raw; N = 4096; dd = 4;
        data_off = 0;      score_off = 25600;  keep_off = 32000;
        t0f = 1.60f;                       // E[count]≈224 of 4096
    } else if (level == 1) {
        logits = lin_logits; raw = lin_raw; parent = blk_raw; parentN = 4096; ef = 4;
        N = 16384; dd = 4;
        data_off = 38400;  score_off = 64000;  keep_off = 70400;
        t0f = 2.15f;                       // E[count]≈259 of 16384
    } else {
        logits = chr_logits; raw = chr_raw; parent = lin_raw; parentN = 16384; ef = 1;
        N = 16384; dd = 16; bez = true;
        data_off = 76800;  score_off = 179200; keep_off = 185600;
        t0f = 2.15f;
    }
    const uint32_t T0 = f2key(t0f);

    const float img_h = tsizes[2 * b + 0];
    const float img_w = tsizes[2 * b + 1];
    const float* lg = logits + (size_t)b * N;
    const float4* lg4 = (const float4*)lg;
    const int N4 = N >> 2;                 // 1024 or 4096

    if (tid == 0) sCandCnt = 0;
    if (tid < 4) sKw[tid] = 0u;
    // zero suppression masks (400 words, 512 threads)
    if (tid < KSEL * 4) sSup[tid] = 0u;
    __syncthreads();

    // ---- 1. fused load + threshold + collect (single pass, batched LDGs) ----
    {
        float4 vreg[8];
        #pragma unroll
        for (int j = 0; j < 8; j++) {
            int i4 = tid + NTHREADS * j;
            vreg[j] = (i4 < N4) ? lg4[i4]
                                : make_float4(-1e30f, -1e30f, -1e30f, -1e30f);
        }
        #pragma unroll
        for (int j = 0; j < 8; j++) {
            int i4 = tid + NTHREADS * j;
            float e[4] = {vreg[j].x, vreg[j].y, vreg[j].z, vreg[j].w};
            #pragma unroll
            for (int q = 0; q < 4; q++) {
                uint32_t kk = f2key(e[q]);
                if (kk >= T0 && i4 < N4) {
                    int gi = 4 * i4 + q;
                    int pos = atomicAdd(&sCandCnt, 1);
                    if (pos < CAND_MAX)
                        sCand[pos] = ~(((unsigned long long)kk << 32) |
                                       (unsigned long long)(0xFFFFFFFFu - (uint32_t)gi));
                }
            }
        }
    }
    __syncthreads();
    int cnt = sCandCnt;

    // ---- 2. fallback (uniform branch, ~never taken on real data) ----
    if (cnt < KSEL || cnt > CAND_MAX) {
        uint32_t lo = 0u, hi = 0xFFFFFFFFu, T = 0u;
        for (int it = 0; it < 34; it++) {
            uint32_t mid = lo + ((hi - lo) >> 1);
            int c = 0;
            #pragma unroll
            for (int j = 0; j < 8; j++) {
                int i4 = tid + NTHREADS * j;
                if (i4 < N4) {
                    float4 v = lg4[i4];
                    c += (f2key(v.x) >= mid) + (f2key(v.y) >= mid)
                       + (f2key(v.z) >= mid) + (f2key(v.w) >= mid);
                }
            }
            #pragma unroll
            for (int d = 16; d > 0; d >>= 1)
                c += __shfl_down_sync(0xffffffffu, c, d);
            if (lane == 0) sPart[it & 1][wid] = c;
            __syncthreads();
            int tot = 0;
            #pragma unroll
            for (int w = 0; w < NWARPS; w++) tot += sPart[it & 1][w];
            if (tot >= KSEL && tot <= CAND_MAX) { T = mid; break; }
            if (tot > CAND_MAX) lo = mid; else hi = mid;
            if (hi - lo <= 1u) { T = lo; break; }
        }
        if (tid == 0) sCandCnt = 0;
        __syncthreads();
        #pragma unroll
        for (int j = 0; j < 8; j++) {
            int i4 = tid + NTHREADS * j;
            if (i4 < N4) {
                float4 v = lg4[i4];
                float e[4] = {v.x, v.y, v.z, v.w};
                #pragma unroll
                for (int q = 0; q < 4; q++) {
                    uint32_t kk = f2key(e[q]);
                    if (kk >= T) {
                        int gi = 4 * i4 + q;
                        int pos = atomicAdd(&sCandCnt, 1);
                        if (pos < CAND_MAX)
                            sCand[pos] = ~(((unsigned long long)kk << 32) |
                                           (unsigned long long)(0xFFFFFFFFu - (uint32_t)gi));
                    }
                }
            }
        }
        __syncthreads();
        cnt = min(sCandCnt, CAND_MAX);
    }

    // ---- 3. enumeration sort: rank & scatter top-100 (1 barrier) ----
    if (tid < KSEL) { sVal[tid] = 0.0f; sIdx[tid] = 0; }
    __syncthreads();
    if (tid < cnt) {
        unsigned long long mine = sCand[tid];
        int rank = 0;
        int j = 0;
        for (; j + 3 < cnt; j += 4)
            rank += (sCand[j]     < mine) + (sCand[j + 1] < mine)
                  + (sCand[j + 2] < mine) + (sCand[j + 3] < mine);
        for (; j < cnt; j++) rank += (sCand[j] < mine);
        if (rank < KSEL) {
            unsigned long long comb = ~mine;
            uint32_t kk  = (uint32_t)(comb >> 32);
            uint32_t idx = 0xFFFFFFFFu - (uint32_t)(comb & 0xFFFFFFFFull);
            sIdx[rank] = (int)idx;
            uint32_t u = (kk & 0x80000000u) ? (kk & 0x7FFFFFFFu) : ~kk;
            float lv = __uint_as_float(u);
            sVal[rank] = 1.0f / (1.0f + expf(-lv));
        }
    }
    __syncthreads();

    // ---- 4. boxes / data ----
    if (tid < KSEL) {
        int si = sIdx[tid];
        if (!bez) {
            const float* r = raw + ((size_t)b * N + si) * 4;
            float cx = r[0], cy = r[1], w = r[2], h = r[3];
            float x1 = (cx - 0.5f * w) * img_w;
            float y1 = (cy - 0.5f * h) * img_h;
            float x2 = (cx + 0.5f * w) * img_w;
            float y2 = (cy + 0.5f * h) * img_h;
            if (level == 0) {
                x1 = fminf(fmaxf(x1, 0.0f), img_w);
                y1 = fminf(fmaxf(y1, 0.0f), img_h);
                x2 = fminf(fmaxf(x2, 0.0f), img_w);
                y2 = fminf(fmaxf(y2, 0.0f), img_h);
            }
            sData[tid * 16 + 0] = x1; sData[tid * 16 + 1] = y1;
            sData[tid * 16 + 2] = x2; sData[tid * 16 + 3] = y2;
            sBox[tid * 4 + 0] = x1; sBox[tid * 4 + 1] = y1;
            sBox[tid * 4 + 2] = x2; sBox[tid * 4 + 3] = y2;
            sArea[tid] = (x2 - x1) * (y2 - y1);
        } else {
            const float* r = raw + ((size_t)b * N + si) * 16;
            float cp0[8], cp1[8];
            #pragma unroll
            for (int f = 0; f < 8; f++) {
                cp0[f] = r[2 * f + 0] * img_h;          // scale_pts = tile((h,w),8)
                cp1[f] = r[2 * f + 1] * img_w;
                sData[tid * 16 + 2 * f + 0] = cp0[f];
                sData[tid * 16 + 2 * f + 1] = cp1[f];
            }
            float mn0 =  INFINITY, mn1 =  INFINITY;
            float mx0 = -INFINITY, mx1 = -INFINITY;
            #pragma unroll
            for (int s = 0; s < SAMPLE_NUM; s++) {
                float t  = (float)s / (float)(SAMPLE_NUM - 1);
                float ti = 1.0f - t;
                float b0c = ti * ti * ti;
                float b1c = 3.0f * t * ti * ti;
                float b2c = 3.0f * t * t * ti;
                float b3c = t * t * t;
                float px = b0c * cp0[0] + b1c * cp0[1] + b2c * cp0[2] + b3c * cp0[3];
                float py = b0c * cp1[0] + b1c * cp1[1] + b2c * cp1[2] + b3c * cp1[3];
                float qx = b0c * cp0[4] + b1c * cp0[5] + b2c * cp0[6] + b3c * cp0[7];
                float qy = b0c * cp1[4] + b1c * cp1[5] + b2c * cp1[6] + b3c * cp1[7];
                mn0 = fminf(mn0, fminf(px, qx));
                mn1 = fminf(mn1, fminf(py, qy));
                mx0 = fmaxf(mx0, fmaxf(px, qx));
                mx1 = fmaxf(mx1, fmaxf(py, qy));
            }
            sBox[tid * 4 + 0] = mn0; sBox[tid * 4 + 1] = mn1;
            sBox[tid * 4 + 2] = mx0; sBox[tid * 4 + 3] = mx1;
            sArea[tid] = (mx0 - mn0) * (mx1 - mn1);
        }
    }

    // ---- 5. keep = vals > 0.1 (fallback to index 0) ----
    int keep0 = (tid < KSEL) ? (sVal[tid] > 0.1f ? 1 : 0) : 0;
    int any0 = __syncthreads_or(keep0);
    if (tid < KSEL) sKeep[tid] = any0 ? keep0 : (tid == 0 ? 1 : 0);

    // ---- 6. parent belong filter (line / char) ----
    if (level > 0) {
        int valid = 0, mykeep = 0;
        if (tid < KSEL) {
            mykeep = sKeep[tid];
            int pi = sIdx[tid] / ef;
            const float* pr = parent + ((size_t)b * parentN + pi) * 4;
            float pcx = pr[0], pcy = pr[1], pw = pr[2], ph = pr[3];
            float px1 = (pcx - 0.5f * pw) * img_w;
            float py1 = (pcy - 0.5f * ph) * img_h;
            float px2 = (pcx + 0.5f * pw) * img_w;
            float py2 = (pcy + 0.5f * ph) * img_h;
            float bx1 = sBox[tid * 4 + 0], by1 = sBox[tid * 4 + 1];
            float bx2 = sBox[tid * 4 + 2], by2 = sBox[tid * 4 + 3];
            float ix1 = fmaxf(bx1, px1), iy1 = fmaxf(by1, py1);
            float ix2 = fminf(bx2, px2), iy2 = fminf(by2, py2);
            float inter = fmaxf(ix2 - ix1, 0.0f) * fmaxf(iy2 - iy1, 0.0f);
            float carea = (bx2 - bx1) * (by2 - by1);
            float belong = inter / (carea + 1e-6f);
            sBelong[tid] = belong;
            valid = (belong > 0.6f) ? 1 : 0;
        }
        int haveValid = __syncthreads_or(valid && mykeep);
        if (!haveValid) {
            if (tid == 0) {
                float best = -INFINITY; int bi = 0;
                for (int kk = 0; kk < KSEL; kk++) {
                    float v = sKeep[kk] ? sBelong[kk] : -INFINITY;
                    if (v > best) { best = v; bi = kk; }
                }
                sFb = bi;
            }
            __syncthreads();
            if (tid < KSEL) valid = (tid == sFb) ? 1 : 0;
        }
        if (tid < KSEL) sKeep[tid] &= valid;
    }
    __syncthreads();

    // ---- 7a. parallel IoU pair masks: 10000 pairs over 512 threads ----
    for (int p = tid; p < KSEL * KSEL; p += NTHREADS) {
        int i = p / KSEL;
        int j = p - i * KSEL;
        if (j > i) {
            float ix1 = fmaxf(sBox[i * 4 + 0], sBox[j * 4 + 0]);
            float iy1 = fmaxf(sBox[i * 4 + 1], sBox[j * 4 + 1]);
            float ix2 = fminf(sBox[i * 4 + 2], sBox[j * 4 + 2]);
            float iy2 = fminf(sBox[i * 4 + 3], sBox[j * 4 + 3]);
            float inter = fmaxf(ix2 - ix1, 0.0f) * fmaxf(iy2 - iy1, 0.0f);
            float iou = inter / (sArea[i] + sArea[j] - inter);
            if (iou > 0.1f)
                atomicOr(&sSup[i * 4 + (j >> 5)], 1u << (j & 31));
        }
    }
    // pack keep bits: warps 0..3 ballot their 32 slots
    if (wid < 4) {
        unsigned bb = __ballot_sync(0xffffffffu,
                                    (tid < KSEL) ? (sKeep[tid] != 0) : false);
        if (lane == 0) sKw[wid] = bb;
    }
    __syncthreads();

    // ---- 7b. greedy cascade over bitmasks: thread 0, ~100 cheap iters ----
    if (tid == 0) {
        uint32_t k0 = sKw[0], k1 = sKw[1], k2 = sKw[2], k3 = sKw[3];
        #pragma unroll 4
        for (int i = 0; i < KSEL; i++) {
            uint32_t kwv = (i < 32) ? k0 : (i < 64) ? k1 : (i < 96) ? k2 : k3;
            uint4 m = *(const uint4*)&sSup[i * 4];     // 16B-aligned: legal LDS.128
            if ((kwv >> (i & 31)) & 1u) {
                k0 &= ~m.x; k1 &= ~m.y; k2 &= ~m.z; k3 &= ~m.w;
            }
        }
        sKw[0] = k0; sKw[1] = k1; sKw[2] = k2; sKw[3] = k3;
    }
    __syncthreads();

    // ---- 8. write outputs ----
    if (tid < KSEL) {
        const int nk = (sKw[tid >> 5] >> (tid & 31)) & 1u;
        for (int j = 0; j < dd; j++)
            out[data_off + ((size_t)b * KSEL + tid) * dd + j] =
                nk ? sData[tid * 16 + j] : 0.0f;
        out[score_off + (size_t)b * KSEL + tid] = nk ? sVal[tid] : 0.0f;
        out[keep_off  + (size_t)b * KSEL + tid] = nk ? 1.0f : 0.0f;
    }
}

extern "C" void kernel_launch(void* const* d_in, const int* in_sizes, int n_in,
                              void* d_out, int out_size) {
    const float* blk_logits = (const float*)d_in[0];
    const float* lin_logits = (const float*)d_in[1];
    const float* chr_logits = (const float*)d_in[2];
    const float* blk_raw    = (const float*)d_in[3];
    const float* lin_raw    = (const float*)d_in[4];
    const float* chr_raw    = (const float*)d_in[5];
    const float* tsizes     = (const float*)d_in[6];
    float* out = (float*)d_out;

    dim3 grid(64, 3);
    postprocess_kernel<<<grid, NTHREADS>>>(
        blk_logits, lin_logits, chr_logits,
        blk_raw, lin_raw, chr_raw, tsizes, out);
}